// round 8
// baseline (speedup 1.0000x reference)
#include <cuda_runtime.h>
#include <cuda_bf16.h>
#include <math_constants.h>

#define NV 8192
#define NF 16384
#define NP 16384
#define NPAIR (NF / 2)
#define TPB 128
#define WPB (TPB / 32)
#define QCAP 256

// Packed per-triangle data: ax,ay,az, bx,by,bz, cx,cy,cz, nx,ny,nz
__device__ __align__(16) float g_tri[NF * 12];
// Plane cull data (intermediate): unit normal xyz, w = -dot(a, n_hat).
__device__ float4 g_plane[NF];
// Pair-interleaved plane data: rec0 = (nx0,nx1,ny0,ny1), rec1 = (nz0,nz1,w0,w1)
__device__ __align__(16) float4 g_pp[NPAIR * 2];

// ---------- packed f32x2 helpers ----------
__device__ __forceinline__ unsigned long long pk2(float lo, float hi) {
    unsigned long long r;
    asm("mov.b64 %0, {%1, %2};" : "=l"(r) : "f"(lo), "f"(hi));
    return r;
}
__device__ __forceinline__ unsigned long long fma2(unsigned long long a,
                                                   unsigned long long b,
                                                   unsigned long long c) {
    unsigned long long d;
    asm("fma.rn.f32x2 %0, %1, %2, %3;" : "=l"(d) : "l"(a), "l"(b), "l"(c));
    return d;
}
__device__ __forceinline__ void upk2(unsigned long long v, float& lo, float& hi) {
    asm("mov.b64 {%0, %1}, %2;" : "=f"(lo), "=f"(hi) : "l"(v));
}

// ---------- strict IEEE helpers (bit-stable vs reference) ----------
__device__ __forceinline__ float dot3(float x0, float x1, float x2,
                                      float y0, float y1, float y2) {
    return __fadd_rn(__fadd_rn(__fmul_rn(x0, y0), __fmul_rn(x1, y1)),
                     __fmul_rn(x2, y2));
}
__device__ __forceinline__ float sdiv(float x, float y) {
    return __fdiv_rn(x, (y == 0.0f) ? 1.0f : y);
}

// ---------- kernel 1: triangle precompute ----------
__global__ void precompute_tris(const float* __restrict__ vertices,
                                const int* __restrict__ faces) {
    int f = blockIdx.x * blockDim.x + threadIdx.x;
    if (f >= NF) return;
    int i0 = faces[f * 3 + 0];
    int i1 = faces[f * 3 + 1];
    int i2 = faces[f * 3 + 2];
    float ax = vertices[i0 * 3 + 0], ay = vertices[i0 * 3 + 1], az = vertices[i0 * 3 + 2];
    float bx = vertices[i1 * 3 + 0], by = vertices[i1 * 3 + 1], bz = vertices[i1 * 3 + 2];
    float cx = vertices[i2 * 3 + 0], cy = vertices[i2 * 3 + 1], cz = vertices[i2 * 3 + 2];
    float abx = __fsub_rn(bx, ax), aby = __fsub_rn(by, ay), abz = __fsub_rn(bz, az);
    float acx = __fsub_rn(cx, ax), acy = __fsub_rn(cy, ay), acz = __fsub_rn(cz, az);
    float nx = __fsub_rn(__fmul_rn(aby, acz), __fmul_rn(abz, acy));
    float ny = __fsub_rn(__fmul_rn(abz, acx), __fmul_rn(abx, acz));
    float nz = __fsub_rn(__fmul_rn(abx, acy), __fmul_rn(aby, acx));
    float* t = &g_tri[f * 12];
    t[0] = ax; t[1] = ay; t[2] = az;
    t[3] = bx; t[4] = by; t[5] = bz;
    t[6] = cx; t[7] = cy; t[8] = cz;
    t[9] = nx; t[10] = ny; t[11] = nz;

    float len2 = nx * nx + ny * ny + nz * nz;
    if (len2 > 0.0f) {
        float inv = rsqrtf(len2);
        float ux = nx * inv, uy = ny * inv, uz = nz * inv;
        float d = ax * ux + ay * uy + az * uz;
        g_plane[f] = make_float4(ux, uy, uz, -d);
    } else {
        g_plane[f] = make_float4(0.0f, 0.0f, 0.0f, 0.0f);  // never culled
    }
}

// ---------- kernel 1b: interleave plane pairs for f32x2 cull ----------
__global__ void pack_pairs() {
    int q = blockIdx.x * blockDim.x + threadIdx.x;
    if (q >= NPAIR) return;
    float4 a = g_plane[2 * q];
    float4 b = g_plane[2 * q + 1];
    g_pp[2 * q + 0] = make_float4(a.x, b.x, a.y, b.y);
    g_pp[2 * q + 1] = make_float4(a.z, b.z, a.w, b.w);
}

// Evaluate one triangle exactly (bit-identical to reference); update lane best.
__device__ __forceinline__ bool eval_tri(
    int fe, float px, float py, float pz,
    unsigned long long& best_key, float& best_sd)
{
    const float4* tq = reinterpret_cast<const float4*>(&g_tri[fe * 12]);
    float4 q0 = __ldg(&tq[0]);
    float4 q1 = __ldg(&tq[1]);
    float4 q2 = __ldg(&tq[2]);
    float ax = q0.x, ay = q0.y, az = q0.z;
    float bx = q0.w, by = q1.x, bz = q1.y;
    float cx = q1.z, cy = q1.w, cz = q2.x;
    float nx = q2.y, ny = q2.z, nz = q2.w;

    float abx = __fsub_rn(bx, ax), aby = __fsub_rn(by, ay), abz = __fsub_rn(bz, az);
    float acx = __fsub_rn(cx, ax), acy = __fsub_rn(cy, ay), acz = __fsub_rn(cz, az);
    float apx = __fsub_rn(px, ax), apy = __fsub_rn(py, ay), apz = __fsub_rn(pz, az);
    float bpx = __fsub_rn(px, bx), bpy = __fsub_rn(py, by), bpz = __fsub_rn(pz, bz);
    float cpx = __fsub_rn(px, cx), cpy = __fsub_rn(py, cy), cpz = __fsub_rn(pz, cz);

    float d1 = dot3(abx, aby, abz, apx, apy, apz);
    float d2 = dot3(acx, acy, acz, apx, apy, apz);
    float d3 = dot3(abx, aby, abz, bpx, bpy, bpz);
    float d4 = dot3(acx, acy, acz, bpx, bpy, bpz);
    float d5 = dot3(abx, aby, abz, cpx, cpy, cpz);
    float d6 = dot3(acx, acy, acz, cpx, cpy, cpz);

    float va = __fsub_rn(__fmul_rn(d3, d6), __fmul_rn(d5, d4));
    float vb = __fsub_rn(__fmul_rn(d5, d2), __fmul_rn(d1, d6));
    float vc = __fsub_rn(__fmul_rn(d1, d4), __fmul_rn(d3, d2));
    float denom = __fadd_rn(__fadd_rn(va, vb), vc);
    float v = sdiv(vb, denom);
    float w = sdiv(vc, denom);

    float e43 = __fsub_rn(d4, d3);
    float e56 = __fsub_rn(d5, d6);
    float t_bc = sdiv(e43, __fadd_rn(e43, e56));
    if (va <= 0.0f && e43 >= 0.0f && e56 >= 0.0f) {
        v = __fsub_rn(1.0f, t_bc); w = t_bc;
    }
    float t_ac = sdiv(d2, __fsub_rn(d2, d6));
    if (vb <= 0.0f && d2 >= 0.0f && d6 <= 0.0f) { v = 0.0f; w = t_ac; }
    float t_ab = sdiv(d1, __fsub_rn(d1, d3));
    if (vc <= 0.0f && d1 >= 0.0f && d3 <= 0.0f) { v = t_ab; w = 0.0f; }
    if (d6 >= 0.0f && d5 <= d6) { v = 0.0f; w = 1.0f; }
    if (d3 >= 0.0f && d4 <= d3) { v = 1.0f; w = 0.0f; }
    if (d1 <= 0.0f && d2 <= 0.0f) { v = 0.0f; w = 0.0f; }

    float clx = __fadd_rn(__fadd_rn(ax, __fmul_rn(v, abx)), __fmul_rn(w, acx));
    float cly = __fadd_rn(__fadd_rn(ay, __fmul_rn(v, aby)), __fmul_rn(w, acy));
    float clz = __fadd_rn(__fadd_rn(az, __fmul_rn(v, abz)), __fmul_rn(w, acz));
    float dx = __fsub_rn(px, clx);
    float dy = __fsub_rn(py, cly);
    float dz = __fsub_rn(pz, clz);
    float dist2 = dot3(dx, dy, dz, dx, dy, dz);

    unsigned long long key =
        ((unsigned long long)__float_as_uint(dist2) << 32) | (unsigned)fe;
    if (key < best_key) {
        best_key = key;
        best_sd = dot3(dx, dy, dz, nx, ny, nz);
        return true;
    }
    return false;
}

// ---------- kernel 2: warp-per-point, f32x2 cull + fast path + prefetch ------
__global__ void __launch_bounds__(TPB) sdf_main(const float* __restrict__ points,
                                                float* __restrict__ out) {
    __shared__ int queue[WPB][QCAP];

    int warp_in_blk = threadIdx.x / 32;
    int lane = threadIdx.x % 32;
    int pid = blockIdx.x * WPB + warp_in_blk;

    float px = points[pid * 3 + 0];
    float py = points[pid * 3 + 1];
    float pz = points[pid * 3 + 2];
    unsigned long long px2 = pk2(px, px);
    unsigned long long py2 = pk2(py, py);
    unsigned long long pz2 = pk2(pz, pz);

    // Seed upper bound from 1024 vertex-a distances
    float ub2 = CUDART_INF_F;
    #pragma unroll 4
    for (int i = 0; i < 32; i++) {
        int f = i * 32 + lane;
        const float4* tq = reinterpret_cast<const float4*>(&g_tri[f * 12]);
        float4 q0 = __ldg(&tq[0]);
        float dx = px - q0.x, dy = py - q0.y, dz = pz - q0.z;
        ub2 = fminf(ub2, fmaf(dx, dx, fmaf(dy, dy, dz * dz)));
    }
    #pragma unroll
    for (int o = 16; o > 0; o >>= 1)
        ub2 = fminf(ub2, __shfl_xor_sync(0xFFFFFFFFu, ub2, o));
    float sq = fmaf(sqrtf(ub2), 1.001f, 1e-6f);  // inflated upper bound on min dist

    unsigned long long best_key = 0xFFFFFFFFFFFFFFFFull;
    float best_sd = 0.0f;

    int qn = 0, qhead = 0;
    unsigned lanemask = (1u << lane) - 1u;

    // Prime prefetch: pairs pA = lane, pB = lane + 32 (chunk 0)
    float4 rA0 = __ldg(&g_pp[(lane) * 2 + 0]);
    float4 rA1 = __ldg(&g_pp[(lane) * 2 + 1]);
    float4 rB0 = __ldg(&g_pp[(lane + 32) * 2 + 0]);
    float4 rB1 = __ldg(&g_pp[(lane + 32) * 2 + 1]);

    for (int chunk = 0; chunk < NF; chunk += 128) {
        // pair A: faces chunk+2*lane, +1 ; pair B: faces chunk+64+2*lane, +1
        unsigned long long accA = fma2(px2, pk2(rA0.x, rA0.y), pk2(rA1.z, rA1.w));
        accA = fma2(py2, pk2(rA0.z, rA0.w), accA);
        accA = fma2(pz2, pk2(rA1.x, rA1.y), accA);
        unsigned long long accB = fma2(px2, pk2(rB0.x, rB0.y), pk2(rB1.z, rB1.w));
        accB = fma2(py2, pk2(rB0.z, rB0.w), accB);
        accB = fma2(pz2, pk2(rB1.x, rB1.y), accB);
        float pd0, pd1, pd2, pd3;
        upk2(accA, pd0, pd1);
        upk2(accB, pd2, pd3);
        bool k0 = (fabsf(pd0) <= sq);
        bool k1 = (fabsf(pd1) <= sq);
        bool k2 = (fabsf(pd2) <= sq);
        bool k3 = (fabsf(pd3) <= sq);

        // Prefetch next chunk's pair records (overlaps compaction + drain)
        int nxt = chunk + 128;
        if (nxt < NF) {
            int pb = nxt >> 1;
            rA0 = __ldg(&g_pp[(pb + lane) * 2 + 0]);
            rA1 = __ldg(&g_pp[(pb + lane) * 2 + 1]);
            rB0 = __ldg(&g_pp[(pb + lane + 32) * 2 + 0]);
            rB1 = __ldg(&g_pp[(pb + lane + 32) * 2 + 1]);
        }

        // Fast path: most chunks have zero survivors warp-wide
        if (__ballot_sync(0xFFFFFFFFu, k0 | k1 | k2 | k3)) {
            unsigned m0 = __ballot_sync(0xFFFFFFFFu, k0);
            unsigned m1 = __ballot_sync(0xFFFFFFFFu, k1);
            unsigned m2 = __ballot_sync(0xFFFFFFFFu, k2);
            unsigned m3 = __ballot_sync(0xFFFFFFFFu, k3);
            int n0 = __popc(m0);
            int n1 = __popc(m1);
            int n2 = __popc(m2);
            if (k0) queue[warp_in_blk][(qhead + qn + __popc(m0 & lanemask)) & (QCAP - 1)] = chunk + 2 * lane;
            if (k1) queue[warp_in_blk][(qhead + qn + n0 + __popc(m1 & lanemask)) & (QCAP - 1)] = chunk + 2 * lane + 1;
            if (k2) queue[warp_in_blk][(qhead + qn + n0 + n1 + __popc(m2 & lanemask)) & (QCAP - 1)] = chunk + 64 + 2 * lane;
            if (k3) queue[warp_in_blk][(qhead + qn + n0 + n1 + n2 + __popc(m3 & lanemask)) & (QCAP - 1)] = chunk + 64 + 2 * lane + 1;
            qn += n0 + n1 + n2 + __popc(m3);
            __syncwarp();

            while (qn >= 32) {
                int fe = queue[warp_in_blk][(qhead + lane) & (QCAP - 1)];
                qhead += 32;
                qn -= 32;
                bool improved = eval_tri(fe, px, py, pz, best_key, best_sd);
                if (__ballot_sync(0xFFFFFFFFu, improved)) {
                    float bd2 = __uint_as_float((unsigned)(best_key >> 32));
                    #pragma unroll
                    for (int o = 16; o > 0; o >>= 1)
                        bd2 = fminf(bd2, __shfl_xor_sync(0xFFFFFFFFu, bd2, o));
                    sq = fminf(sq, fmaf(sqrtf(bd2), 1.001f, 1e-6f));
                }
            }
            __syncwarp();
        }
    }

    // Drain remaining queued survivors
    if (lane < qn) {
        int fe = queue[warp_in_blk][(qhead + lane) & (QCAP - 1)];
        eval_tri(fe, px, py, pz, best_key, best_sd);
    }
    __syncwarp();

    // Warp-reduce (key, sd) lexicographic min — matches argmin first-index tie-break
    #pragma unroll
    for (int o = 16; o > 0; o >>= 1) {
        unsigned long long ok = __shfl_xor_sync(0xFFFFFFFFu, best_key, o);
        float osd = __shfl_xor_sync(0xFFFFFFFFu, best_sd, o);
        if (ok < best_key) { best_key = ok; best_sd = osd; }
    }

    if (lane == 0) {
        float dist2 = __uint_as_float((unsigned)(best_key >> 32));
        float dist = sqrtf(fmaxf(dist2, 1e-12f));
        out[pid] = (best_sd > 0.0f) ? -dist : dist;
    }
}

extern "C" void kernel_launch(void* const* d_in, const int* in_sizes, int n_in,
                              void* d_out, int out_size) {
    const float* points   = (const float*)d_in[0];
    const float* vertices = (const float*)d_in[1];
    const int*   faces    = (const int*)d_in[2];
    float* out = (float*)d_out;

    precompute_tris<<<(NF + 255) / 256, 256>>>(vertices, faces);
    pack_pairs<<<(NPAIR + 255) / 256, 256>>>();
    sdf_main<<<NP / WPB, TPB>>>(points, out);
}

// round 9
// speedup vs baseline: 1.2850x; 1.2850x over previous
#include <cuda_runtime.h>
#include <cuda_bf16.h>
#include <math_constants.h>

#define NV 8192
#define NF 16384
#define NP 16384
#define TPB 128
#define WPB (TPB / 32)
#define QCAP 256

// Packed per-triangle data: ax,ay,az, bx,by,bz, cx,cy,cz, nx,ny,nz
__device__ __align__(16) float g_tri[NF * 12];
// Plane cull data: unit normal xyz, w = -dot(a, n_hat). Zero if degenerate.
__device__ float4 g_plane[NF];

// ---------- strict IEEE helpers (bit-stable vs reference) ----------
__device__ __forceinline__ float dot3(float x0, float x1, float x2,
                                      float y0, float y1, float y2) {
    return __fadd_rn(__fadd_rn(__fmul_rn(x0, y0), __fmul_rn(x1, y1)),
                     __fmul_rn(x2, y2));
}
__device__ __forceinline__ float sdiv(float x, float y) {
    return __fdiv_rn(x, (y == 0.0f) ? 1.0f : y);
}

// ---------- kernel 1: triangle precompute ----------
__global__ void precompute_tris(const float* __restrict__ vertices,
                                const int* __restrict__ faces) {
    int f = blockIdx.x * blockDim.x + threadIdx.x;
    if (f >= NF) return;
    int i0 = faces[f * 3 + 0];
    int i1 = faces[f * 3 + 1];
    int i2 = faces[f * 3 + 2];
    float ax = vertices[i0 * 3 + 0], ay = vertices[i0 * 3 + 1], az = vertices[i0 * 3 + 2];
    float bx = vertices[i1 * 3 + 0], by = vertices[i1 * 3 + 1], bz = vertices[i1 * 3 + 2];
    float cx = vertices[i2 * 3 + 0], cy = vertices[i2 * 3 + 1], cz = vertices[i2 * 3 + 2];
    float abx = __fsub_rn(bx, ax), aby = __fsub_rn(by, ay), abz = __fsub_rn(bz, az);
    float acx = __fsub_rn(cx, ax), acy = __fsub_rn(cy, ay), acz = __fsub_rn(cz, az);
    float nx = __fsub_rn(__fmul_rn(aby, acz), __fmul_rn(abz, acy));
    float ny = __fsub_rn(__fmul_rn(abz, acx), __fmul_rn(abx, acz));
    float nz = __fsub_rn(__fmul_rn(abx, acy), __fmul_rn(aby, acx));
    float* t = &g_tri[f * 12];
    t[0] = ax; t[1] = ay; t[2] = az;
    t[3] = bx; t[4] = by; t[5] = bz;
    t[6] = cx; t[7] = cy; t[8] = cz;
    t[9] = nx; t[10] = ny; t[11] = nz;

    // Plane for culling (approx math fine: used only behind safety margins)
    float len2 = nx * nx + ny * ny + nz * nz;
    if (len2 > 0.0f) {
        float inv = rsqrtf(len2);
        float ux = nx * inv, uy = ny * inv, uz = nz * inv;
        float d = ax * ux + ay * uy + az * uz;
        g_plane[f] = make_float4(ux, uy, uz, -d);
    } else {
        g_plane[f] = make_float4(0.0f, 0.0f, 0.0f, 0.0f);  // never culled
    }
}

// Evaluate one triangle exactly (bit-identical to reference); update lane best.
// Returns true if this lane's best improved.
__device__ __forceinline__ bool eval_tri(
    int fe, float px, float py, float pz,
    unsigned long long& best_key, float& best_sd)
{
    const float4* tq = reinterpret_cast<const float4*>(&g_tri[fe * 12]);
    float4 q0 = __ldg(&tq[0]);
    float4 q1 = __ldg(&tq[1]);
    float4 q2 = __ldg(&tq[2]);
    float ax = q0.x, ay = q0.y, az = q0.z;
    float bx = q0.w, by = q1.x, bz = q1.y;
    float cx = q1.z, cy = q1.w, cz = q2.x;
    float nx = q2.y, ny = q2.z, nz = q2.w;

    float abx = __fsub_rn(bx, ax), aby = __fsub_rn(by, ay), abz = __fsub_rn(bz, az);
    float acx = __fsub_rn(cx, ax), acy = __fsub_rn(cy, ay), acz = __fsub_rn(cz, az);
    float apx = __fsub_rn(px, ax), apy = __fsub_rn(py, ay), apz = __fsub_rn(pz, az);
    float bpx = __fsub_rn(px, bx), bpy = __fsub_rn(py, by), bpz = __fsub_rn(pz, bz);
    float cpx = __fsub_rn(px, cx), cpy = __fsub_rn(py, cy), cpz = __fsub_rn(pz, cz);

    float d1 = dot3(abx, aby, abz, apx, apy, apz);
    float d2 = dot3(acx, acy, acz, apx, apy, apz);
    float d3 = dot3(abx, aby, abz, bpx, bpy, bpz);
    float d4 = dot3(acx, acy, acz, bpx, bpy, bpz);
    float d5 = dot3(abx, aby, abz, cpx, cpy, cpz);
    float d6 = dot3(acx, acy, acz, cpx, cpy, cpz);

    float va = __fsub_rn(__fmul_rn(d3, d6), __fmul_rn(d5, d4));
    float vb = __fsub_rn(__fmul_rn(d5, d2), __fmul_rn(d1, d6));
    float vc = __fsub_rn(__fmul_rn(d1, d4), __fmul_rn(d3, d2));
    float denom = __fadd_rn(__fadd_rn(va, vb), vc);
    float v = sdiv(vb, denom);
    float w = sdiv(vc, denom);

    float e43 = __fsub_rn(d4, d3);
    float e56 = __fsub_rn(d5, d6);
    float t_bc = sdiv(e43, __fadd_rn(e43, e56));
    if (va <= 0.0f && e43 >= 0.0f && e56 >= 0.0f) {
        v = __fsub_rn(1.0f, t_bc); w = t_bc;
    }
    float t_ac = sdiv(d2, __fsub_rn(d2, d6));
    if (vb <= 0.0f && d2 >= 0.0f && d6 <= 0.0f) { v = 0.0f; w = t_ac; }
    float t_ab = sdiv(d1, __fsub_rn(d1, d3));
    if (vc <= 0.0f && d1 >= 0.0f && d3 <= 0.0f) { v = t_ab; w = 0.0f; }
    if (d6 >= 0.0f && d5 <= d6) { v = 0.0f; w = 1.0f; }
    if (d3 >= 0.0f && d4 <= d3) { v = 1.0f; w = 0.0f; }
    if (d1 <= 0.0f && d2 <= 0.0f) { v = 0.0f; w = 0.0f; }

    float clx = __fadd_rn(__fadd_rn(ax, __fmul_rn(v, abx)), __fmul_rn(w, acx));
    float cly = __fadd_rn(__fadd_rn(ay, __fmul_rn(v, aby)), __fmul_rn(w, acy));
    float clz = __fadd_rn(__fadd_rn(az, __fmul_rn(v, abz)), __fmul_rn(w, acz));
    float dx = __fsub_rn(px, clx);
    float dy = __fsub_rn(py, cly);
    float dz = __fsub_rn(pz, clz);
    float dist2 = dot3(dx, dy, dz, dx, dy, dz);

    unsigned long long key =
        ((unsigned long long)__float_as_uint(dist2) << 32) | (unsigned)fe;
    if (key < best_key) {
        best_key = key;
        best_sd = dot3(dx, dy, dz, nx, ny, nz);
        return true;
    }
    return false;
}

// ---------- kernel 2: warp-per-point, 4-wide scalar cull + prefetch + fast path
__global__ void __launch_bounds__(TPB) sdf_main(const float* __restrict__ points,
                                                float* __restrict__ out) {
    __shared__ int queue[WPB][QCAP];

    int warp_in_blk = threadIdx.x / 32;
    int lane = threadIdx.x % 32;
    int pid = blockIdx.x * WPB + warp_in_blk;

    float px = points[pid * 3 + 0];
    float py = points[pid * 3 + 1];
    float pz = points[pid * 3 + 2];

    // Seed upper bound from 1024 vertex-a distances
    float ub2 = CUDART_INF_F;
    #pragma unroll 4
    for (int i = 0; i < 32; i++) {
        int f = i * 32 + lane;
        const float4* tq = reinterpret_cast<const float4*>(&g_tri[f * 12]);
        float4 q0 = __ldg(&tq[0]);
        float dx = px - q0.x, dy = py - q0.y, dz = pz - q0.z;
        ub2 = fminf(ub2, fmaf(dx, dx, fmaf(dy, dy, dz * dz)));
    }
    #pragma unroll
    for (int o = 16; o > 0; o >>= 1)
        ub2 = fminf(ub2, __shfl_xor_sync(0xFFFFFFFFu, ub2, o));
    float sq = fmaf(sqrtf(ub2), 1.001f, 1e-6f);  // inflated upper bound on min dist

    unsigned long long best_key = 0xFFFFFFFFFFFFFFFFull;
    float best_sd = 0.0f;

    int qn = 0, qhead = 0;
    unsigned lanemask = (1u << lane) - 1u;

    // Prime the prefetch pipeline
    float4 pl0 = __ldg(&g_plane[lane]);
    float4 pl1 = __ldg(&g_plane[lane + 32]);
    float4 pl2 = __ldg(&g_plane[lane + 64]);
    float4 pl3 = __ldg(&g_plane[lane + 96]);

    for (int chunk = 0; chunk < NF; chunk += 128) {
        float pd0 = fabsf(fmaf(px, pl0.x, fmaf(py, pl0.y, fmaf(pz, pl0.z, pl0.w))));
        float pd1 = fabsf(fmaf(px, pl1.x, fmaf(py, pl1.y, fmaf(pz, pl1.z, pl1.w))));
        float pd2 = fabsf(fmaf(px, pl2.x, fmaf(py, pl2.y, fmaf(pz, pl2.z, pl2.w))));
        float pd3 = fabsf(fmaf(px, pl3.x, fmaf(py, pl3.y, fmaf(pz, pl3.z, pl3.w))));
        bool k0 = (pd0 <= sq);
        bool k1 = (pd1 <= sq);
        bool k2 = (pd2 <= sq);
        bool k3 = (pd3 <= sq);

        // Prefetch next chunk's planes (overlaps compaction/drain or fast path)
        int nxt = chunk + 128;
        if (nxt < NF) {
            pl0 = __ldg(&g_plane[nxt + lane]);
            pl1 = __ldg(&g_plane[nxt + lane + 32]);
            pl2 = __ldg(&g_plane[nxt + lane + 64]);
            pl3 = __ldg(&g_plane[nxt + lane + 96]);
        }

        // Fast path: ~60% of chunks have zero survivors warp-wide
        if (!__ballot_sync(0xFFFFFFFFu, k0 | k1 | k2 | k3)) continue;

        unsigned m0 = __ballot_sync(0xFFFFFFFFu, k0);
        unsigned m1 = __ballot_sync(0xFFFFFFFFu, k1);
        unsigned m2 = __ballot_sync(0xFFFFFFFFu, k2);
        unsigned m3 = __ballot_sync(0xFFFFFFFFu, k3);
        int n0 = __popc(m0);
        int n1 = __popc(m1);
        int n2 = __popc(m2);
        if (k0) queue[warp_in_blk][(qhead + qn + __popc(m0 & lanemask)) & (QCAP - 1)] = chunk + lane;
        if (k1) queue[warp_in_blk][(qhead + qn + n0 + __popc(m1 & lanemask)) & (QCAP - 1)] = chunk + lane + 32;
        if (k2) queue[warp_in_blk][(qhead + qn + n0 + n1 + __popc(m2 & lanemask)) & (QCAP - 1)] = chunk + lane + 64;
        if (k3) queue[warp_in_blk][(qhead + qn + n0 + n1 + n2 + __popc(m3 & lanemask)) & (QCAP - 1)] = chunk + lane + 96;
        qn += n0 + n1 + n2 + __popc(m3);
        __syncwarp();

        while (qn >= 32) {
            int fe = queue[warp_in_blk][(qhead + lane) & (QCAP - 1)];
            qhead += 32;
            qn -= 32;
            bool improved = eval_tri(fe, px, py, pz, best_key, best_sd);
            if (__ballot_sync(0xFFFFFFFFu, improved)) {
                float bd2 = __uint_as_float((unsigned)(best_key >> 32));
                #pragma unroll
                for (int o = 16; o > 0; o >>= 1)
                    bd2 = fminf(bd2, __shfl_xor_sync(0xFFFFFFFFu, bd2, o));
                sq = fminf(sq, fmaf(sqrtf(bd2), 1.001f, 1e-6f));
            }
        }
        __syncwarp();
    }

    // Drain remaining queued survivors
    if (lane < qn) {
        int fe = queue[warp_in_blk][(qhead + lane) & (QCAP - 1)];
        eval_tri(fe, px, py, pz, best_key, best_sd);
    }
    __syncwarp();

    // Warp-reduce (key, sd) lexicographic min — matches argmin first-index tie-break
    #pragma unroll
    for (int o = 16; o > 0; o >>= 1) {
        unsigned long long ok = __shfl_xor_sync(0xFFFFFFFFu, best_key, o);
        float osd = __shfl_xor_sync(0xFFFFFFFFu, best_sd, o);
        if (ok < best_key) { best_key = ok; best_sd = osd; }
    }

    if (lane == 0) {
        float dist2 = __uint_as_float((unsigned)(best_key >> 32));
        float dist = sqrtf(fmaxf(dist2, 1e-12f));
        out[pid] = (best_sd > 0.0f) ? -dist : dist;
    }
}

extern "C" void kernel_launch(void* const* d_in, const int* in_sizes, int n_in,
                              void* d_out, int out_size) {
    const float* points   = (const float*)d_in[0];
    const float* vertices = (const float*)d_in[1];
    const int*   faces    = (const int*)d_in[2];
    float* out = (float*)d_out;

    precompute_tris<<<(NF + 255) / 256, 256>>>(vertices, faces);
    sdf_main<<<NP / WPB, TPB>>>(points, out);
}